// round 7
// baseline (speedup 1.0000x reference)
#include <cuda_runtime.h>
#include <cuda_bf16.h>
#include <cstdint>

// norm_conv via mma.sync bf16-split implicit GEMM.
// out = ((im2col(a)-mean)/std) @ W == (conv3x3(a,W) - mean*colsum(W)) * rstd
// Per CTA: 128-pixel tile (4 rows) of one batch, 8 warps.
// Warp = 32 pixels (one image row, two m16 tiles) x 32 out channels (half).
// Both A and B operands via ldmatrix.x4; 3-term bf16 split products with
// term-grouped MMA ordering (same-acc dependency distance 4).

#define SM_WSUM 0                      // 64 f
#define SM_MEAN 256                    // 128 f
#define SM_RSTD 768                    // 128 f
#define SM_S1   1280                   // 204 f
#define SM_S2   2096                   // 204 f
#define SM_B0   3072                   // 2 x B_BYTES double buffer
#define B_BYTES 18432                  // per tap: hi[64][72] + lo[64][72] bf16
#define SM_HI   (SM_B0 + 2 * B_BYTES)  // 39936: [204 pix][36 words] bf16x2
#define SM_LO   (SM_HI + 204 * 36 * 4) // 69312
#define SMEM_TOTAL (SM_LO + 204 * 36 * 4)   // 98688 bytes -> 2 CTAs/SM
#define IN_W    36                     // u32 words per pixel (64ch + pad)

__device__ float g_wsum[64];
__device__ __align__(16) __nv_bfloat16 g_wtp[9 * 2 * 64 * 72]; // [tap][hl][o][k]

__device__ __forceinline__ int refl(int i) {
    i = (i < 0) ? -i : i;
    return (i >= 32) ? 62 - i : i;
}

#define CVT_BF16X2(res, f0, f1) \
    asm("cvt.rn.satfinite.bf16x2.f32 %0, %1, %2;" : "=r"(res) : "f"(f1), "f"(f0))

#define CP_ASYNC16(dst, src) \
    asm volatile("cp.async.cg.shared.global [%0], [%1], 16;" \
                 :: "r"(dst), "l"(src) : "memory")
#define CP_COMMIT() asm volatile("cp.async.commit_group;" ::: "memory")
#define CP_WAIT(n)  asm volatile("cp.async.wait_group %0;" :: "n"(n) : "memory")

#define MMA16816(c, a0, a1, a2, a3, b0, b1) \
    asm volatile("mma.sync.aligned.m16n8k16.row.col.f32.bf16.bf16.f32 " \
        "{%0,%1,%2,%3}, {%4,%5,%6,%7}, {%8,%9}, {%0,%1,%2,%3};" \
        : "+f"((c)[0]), "+f"((c)[1]), "+f"((c)[2]), "+f"((c)[3]) \
        : "r"(a0), "r"(a1), "r"(a2), "r"(a3), "r"(b0), "r"(b1))

#define LDSM_X4(r0, r1, r2, r3, addr) \
    asm volatile("ldmatrix.sync.aligned.m8n8.x4.shared.b16 {%0,%1,%2,%3}, [%4];" \
        : "=r"(r0), "=r"(r1), "=r"(r2), "=r"(r3) : "r"(addr))

// blocks 0..323: bf16 hi/lo split of W into g_wtp[tap][hl][o][k] (k padded 72).
// block 324: column sums of W into g_wsum.
__global__ void prep_kernel(const float* __restrict__ w) {
    if (blockIdx.x == 324) {
        int t = threadIdx.x;
        int o = t >> 2, q = t & 3;
        float s = 0.f;
        for (int p = q; p < 576; p += 4) s += w[p * 64 + o];
        s += __shfl_xor_sync(0xffffffffu, s, 1);
        s += __shfl_xor_sync(0xffffffffu, s, 2);
        if (q == 0) g_wsum[o] = s;
        return;
    }
    int idx = blockIdx.x * 256 + threadIdx.x;   // < 82944 == 9*2*64*72
    int k = idx % 72;
    int rest = idx / 72;
    int o = rest & 63;
    rest >>= 6;
    int hl = rest & 1, tap = rest >> 1;
    __nv_bfloat16 v = __float2bfloat16(0.f);
    if (k < 64) {
        float f = w[(k * 9 + tap) * 64 + o];
        __nv_bfloat16 hi = __float2bfloat16(f);
        v = (hl == 0) ? hi : __float2bfloat16(f - __bfloat162float(hi));
    }
    g_wtp[idx] = v;
}

__global__ __launch_bounds__(256, 2)
void conv_mma_kernel(const float* __restrict__ a, float* __restrict__ out) {
    extern __shared__ char smem[];
    float* smf = (float*)smem;
    uint32_t sb;
    asm("{ .reg .u64 t; cvta.to.shared.u64 t, %1; cvt.u32.u64 %0, t; }"
        : "=r"(sb) : "l"(smem));

    const int t = threadIdx.x;
    const int wrp = t >> 5, l = t & 31;
    const int b = blockIdx.x >> 3;
    const int row0 = (blockIdx.x & 7) << 2;
    const float* A = a + (size_t)b * 65536;

    // prefetch B tap0 into buffer 0
    {
        const char* src = (const char*)g_wtp;
        for (int i = t; i < B_BYTES / 16; i += 256)
            CP_ASYNC16(sb + SM_B0 + i * 16, __cvta_generic_to_global(src + i * 16));
        CP_COMMIT();
    }
    if (t < 64) smf[SM_WSUM / 4 + t] = g_wsum[t];

    // stage + bf16-split input tile into pixel-major hi/lo planes.
    // word (pix, cw) holds channels (2cw, 2cw+1) of pixel pix.
    {
        uint32_t* hip = (uint32_t*)(smem + SM_HI);
        uint32_t* lop = (uint32_t*)(smem + SM_LO);
        for (int idx = t; idx < 32 * 204; idx += 256) {
            int cw = idx / 204, pix = idx - cw * 204;
            int ry = pix / 34, cx = pix - ry * 34;
            int py = refl(row0 - 1 + ry), px = refl(cx - 1);
            const float* p = A + (2 * cw) * 1024 + py * 32 + px;
            float f0 = p[0], f1 = p[1024];
            uint32_t hx; CVT_BF16X2(hx, f0, f1);
            float h0 = __uint_as_float(hx << 16);
            float h1 = __uint_as_float(hx & 0xffff0000u);
            uint32_t lx; CVT_BF16X2(lx, f0 - h0, f1 - h1);
            hip[pix * IN_W + cw] = hx;
            lop[pix * IN_W + cw] = lx;
        }
    }
    __syncthreads();

    // stats: channel reduce (reconstruct v = hi + lo), then 3x3 box sums
    if (t < 204) {
        const uint32_t* hip = (const uint32_t*)(smem + SM_HI) + t * IN_W;
        const uint32_t* lop = (const uint32_t*)(smem + SM_LO) + t * IN_W;
        float s1 = 0.f, s2 = 0.f;
        #pragma unroll 8
        for (int w = 0; w < 32; ++w) {
            uint32_t hx = hip[w], lx = lop[w];
            float f0 = __uint_as_float(hx << 16) + __uint_as_float(lx << 16);
            float f1 = __uint_as_float(hx & 0xffff0000u) +
                       __uint_as_float(lx & 0xffff0000u);
            s1 += f0 + f1;
            s2 += f0 * f0 + f1 * f1;
        }
        smf[SM_S1 / 4 + t] = s1;
        smf[SM_S2 / 4 + t] = s2;
    }
    __syncthreads();
    if (t < 128) {
        int r = t >> 5, x = t & 31;
        float s1 = 0.f, s2 = 0.f;
        #pragma unroll
        for (int dr = 0; dr < 3; ++dr)
            #pragma unroll
            for (int dc = 0; dc < 3; ++dc) {
                int i = (r + dr) * 34 + x + dc;
                s1 += smf[SM_S1 / 4 + i];
                s2 += smf[SM_S2 / 4 + i];
            }
        float mean = s1 * (1.f / 576.f);
        float var  = (s2 - s1 * s1 * (1.f / 576.f)) * (1.f / 575.f);
        smf[SM_MEAN / 4 + t] = mean;
        smf[SM_RSTD / 4 + t] = rsqrtf(fmaxf(var, 1e-30f));
    }

    // warp tile: image row (wrp>>1), 32 pixels (2 m16 tiles), out half wrp&1
    const int g = l >> 2, tg = l & 3;
    const int row = wrp >> 1, h = wrp & 1;

    // ldmatrix lane offsets.
    // B (frags b0=k0,b1=k+8 within n-tile; r2,r3 = next n-tile):
    //   row-sel(+8n) = (l>>4)&1, col-sel(+16B) = (l>>3)&1
    // A (frags a0=(row,k0), a1=(row+8,k0), a2=(row,k+8), a3=(row+8,k+8)):
    //   row-sel(+8pix) = (l>>3)&1, col-sel(+16B) = (l>>4)&1
    const uint32_t b_lane =
        (uint32_t)((((l >> 4) & 1) * 8 + (l & 7)) * 144 + ((l >> 3) & 1) * 16);
    const uint32_t a_lane =
        (uint32_t)((((l >> 3) & 1) * 8 + (l & 7)) * 144 + ((l >> 4) & 1) * 16);

    float acc[2][4][4];
    #pragma unroll
    for (int i = 0; i < 2; ++i)
        #pragma unroll
        for (int j = 0; j < 4; ++j)
            #pragma unroll
            for (int q = 0; q < 4; ++q) acc[i][j][q] = 0.f;

    int buf = 0;
    for (int tap = 0; tap < 9; ++tap) {
        CP_WAIT(0);
        __syncthreads();
        if (tap < 8) {
            const char* src = (const char*)g_wtp + (size_t)(tap + 1) * B_BYTES;
            uint32_t dst = sb + SM_B0 + (buf ^ 1) * B_BYTES;
            for (int i = t; i < B_BYTES / 16; i += 256)
                CP_ASYNC16(dst + i * 16, __cvta_generic_to_global(src + i * 16));
            CP_COMMIT();
        }

        const int dy = tap / 3, dx = tap - dy * 3;
        const uint32_t pixbase = (uint32_t)((row + dy) * 34 + dx) * 144u;
        const uint32_t A0 = sb + SM_HI + pixbase + a_lane;        // tile0 hi
        const uint32_t A1 = A0 + 16 * 144;                        // tile1 hi
        const uint32_t L0 = sb + SM_LO + pixbase + a_lane;        // tile0 lo
        const uint32_t L1 = L0 + 16 * 144;
        const uint32_t Bh = sb + SM_B0 + buf * B_BYTES + h * 4608 + b_lane;
        const uint32_t Bl = Bh + 9216;

        #pragma unroll
        for (int kc = 0; kc < 4; ++kc) {
            const uint32_t ka = (uint32_t)kc * 32u;
            uint32_t ah00, ah01, ah02, ah03, ah10, ah11, ah12, ah13;
            uint32_t al00, al01, al02, al03, al10, al11, al12, al13;
            LDSM_X4(ah00, ah01, ah02, ah03, A0 + ka);
            LDSM_X4(ah10, ah11, ah12, ah13, A1 + ka);
            LDSM_X4(al00, al01, al02, al03, L0 + ka);
            LDSM_X4(al10, al11, al12, al13, L1 + ka);

            #pragma unroll
            for (int j = 0; j < 2; ++j) {
                const uint32_t addr = (uint32_t)(j * 2304) + ka;
                uint32_t bh0, bh1, bh2, bh3, bl0, bl1, bl2, bl3;
                LDSM_X4(bh0, bh1, bh2, bh3, Bh + addr);
                LDSM_X4(bl0, bl1, bl2, bl3, Bl + addr);
                // term hh (4 distinct accs)
                MMA16816(acc[0][2 * j],     ah00, ah01, ah02, ah03, bh0, bh1);
                MMA16816(acc[1][2 * j],     ah10, ah11, ah12, ah13, bh0, bh1);
                MMA16816(acc[0][2 * j + 1], ah00, ah01, ah02, ah03, bh2, bh3);
                MMA16816(acc[1][2 * j + 1], ah10, ah11, ah12, ah13, bh2, bh3);
                // term hl
                MMA16816(acc[0][2 * j],     ah00, ah01, ah02, ah03, bl0, bl1);
                MMA16816(acc[1][2 * j],     ah10, ah11, ah12, ah13, bl0, bl1);
                MMA16816(acc[0][2 * j + 1], ah00, ah01, ah02, ah03, bl2, bl3);
                MMA16816(acc[1][2 * j + 1], ah10, ah11, ah12, ah13, bl2, bl3);
                // term lh
                MMA16816(acc[0][2 * j],     al00, al01, al02, al03, bh0, bh1);
                MMA16816(acc[1][2 * j],     al10, al11, al12, al13, bh0, bh1);
                MMA16816(acc[0][2 * j + 1], al00, al01, al02, al03, bh2, bh3);
                MMA16816(acc[1][2 * j + 1], al10, al11, al12, al13, bh2, bh3);
            }
        }
        buf ^= 1;
    }

    // epilogue: (acc - mean*wsum) * rstd
    float* ob = out + (size_t)b * 65536 + (size_t)(row0 + row) * 32;
    #pragma unroll
    for (int t2 = 0; t2 < 2; ++t2) {
        const int x0 = t2 * 16 + g;
        const int pp = row * 32 + x0;
        const float mean0 = smf[SM_MEAN / 4 + pp],     rstd0 = smf[SM_RSTD / 4 + pp];
        const float mean1 = smf[SM_MEAN / 4 + pp + 8], rstd1 = smf[SM_RSTD / 4 + pp + 8];
        #pragma unroll
        for (int nc = 0; nc < 4; ++nc) {
            const int o0 = h * 32 + nc * 8 + tg * 2;
            const float ws0 = smf[SM_WSUM / 4 + o0];
            const float ws1 = smf[SM_WSUM / 4 + o0 + 1];
            ob[(size_t)o0 * 1024 + x0]           = (acc[t2][nc][0] - mean0 * ws0) * rstd0;
            ob[(size_t)(o0 + 1) * 1024 + x0]     = (acc[t2][nc][1] - mean0 * ws1) * rstd0;
            ob[(size_t)o0 * 1024 + x0 + 8]       = (acc[t2][nc][2] - mean1 * ws0) * rstd1;
            ob[(size_t)(o0 + 1) * 1024 + x0 + 8] = (acc[t2][nc][3] - mean1 * ws1) * rstd1;
        }
    }
}

extern "C" void kernel_launch(void* const* d_in, const int* in_sizes, int n_in,
                              void* d_out, int out_size) {
    const float* a = (const float*)d_in[0];   // [256,64,32,32]
    const float* w = (const float*)d_in[1];   // [576,64]
    float* out = (float*)d_out;

    cudaFuncSetAttribute(conv_mma_kernel,
                         cudaFuncAttributeMaxDynamicSharedMemorySize, SMEM_TOTAL);

    prep_kernel<<<325, 256>>>(w);
    conv_mma_kernel<<<2048, 256, SMEM_TOTAL>>>(a, out);
}

// round 8
// speedup vs baseline: 1.2871x; 1.2871x over previous
#include <cuda_runtime.h>
#include <cuda_fp16.h>
#include <cstdint>

// norm_conv via mma.sync fp16 2-term-split implicit GEMM.
// out = ((im2col(a)-mean)/std) @ W == (conv3x3(a,W) - mean*colsum(W)) * rstd
// Input split x = xh + xl (fp16 each); W rounded once to fp16.
// conv = sum (xh+xl)*wh  -> only W-rounding error (~2-3e-4 aggregate).
// Per CTA: 128-pixel tile (4 rows) of one batch, 8 warps.
// Warp = 32 pixels (2 m16 tiles) x 32 out channels. A,B via ldmatrix.x4.

#define SM_WSUM 0                      // 64 f
#define SM_MEAN 256                    // 128 f
#define SM_RSTD 768                    // 128 f
#define SM_S1   1280                   // 204 f
#define SM_S2   2096                   // 204 f
#define SM_B0   3072                   // 2 x B_BYTES double buffer
#define B_BYTES 9216                   // per tap: wh[64][72] fp16
#define SM_HI   (SM_B0 + 2 * B_BYTES)  // 21504: [204 pix][36 words] f16x2
#define SM_LO   (SM_HI + 204 * 36 * 4) // 50880
#define SMEM_TOTAL (SM_LO + 204 * 36 * 4)   // 80256 bytes -> 2 CTAs/SM
#define IN_W    36                     // u32 words per pixel (64ch + pad)

__device__ float g_wsum[64];
__device__ __align__(16) __half g_wtp[9 * 64 * 72];   // [tap][o][k] fp16

__device__ __forceinline__ int refl(int i) {
    i = (i < 0) ? -i : i;
    return (i >= 32) ? 62 - i : i;
}

// pack two f32 into f16x2: lo = f0, hi = f1
#define CVT_F16X2(res, f0, f1) \
    asm("cvt.rn.f16x2.f32 %0, %1, %2;" : "=r"(res) : "f"(f1), "f"(f0))

#define CP_ASYNC16(dst, src) \
    asm volatile("cp.async.cg.shared.global [%0], [%1], 16;" \
                 :: "r"(dst), "l"(src) : "memory")
#define CP_COMMIT() asm volatile("cp.async.commit_group;" ::: "memory")
#define CP_WAIT(n)  asm volatile("cp.async.wait_group %0;" :: "n"(n) : "memory")

#define MMA16816(c, a0, a1, a2, a3, b0, b1) \
    asm volatile("mma.sync.aligned.m16n8k16.row.col.f32.f16.f16.f32 " \
        "{%0,%1,%2,%3}, {%4,%5,%6,%7}, {%8,%9}, {%0,%1,%2,%3};" \
        : "+f"((c)[0]), "+f"((c)[1]), "+f"((c)[2]), "+f"((c)[3]) \
        : "r"(a0), "r"(a1), "r"(a2), "r"(a3), "r"(b0), "r"(b1))

#define LDSM_X4(r0, r1, r2, r3, addr) \
    asm volatile("ldmatrix.sync.aligned.m8n8.x4.shared.b16 {%0,%1,%2,%3}, [%4];" \
        : "=r"(r0), "=r"(r1), "=r"(r2), "=r"(r3) : "r"(addr))

// blocks 0..161: fp16 W into g_wtp[tap][o][k] (k padded to 72, zero-filled).
// block 162: column sums of W into g_wsum (fp32 exact).
__global__ void prep_kernel(const float* __restrict__ w) {
    if (blockIdx.x == 162) {
        int t = threadIdx.x;
        int o = t >> 2, q = t & 3;
        float s = 0.f;
        for (int p = q; p < 576; p += 4) s += w[p * 64 + o];
        s += __shfl_xor_sync(0xffffffffu, s, 1);
        s += __shfl_xor_sync(0xffffffffu, s, 2);
        if (q == 0) g_wsum[o] = s;
        return;
    }
    int idx = blockIdx.x * 256 + threadIdx.x;   // < 41472 == 9*64*72
    int k = idx % 72;
    int rest = idx / 72;
    int o = rest & 63, tap = rest >> 6;
    __half v = __float2half(0.f);
    if (k < 64) v = __float2half(w[(k * 9 + tap) * 64 + o]);
    g_wtp[idx] = v;
}

__global__ __launch_bounds__(256, 2)
void conv_mma_kernel(const float* __restrict__ a, float* __restrict__ out) {
    extern __shared__ char smem[];
    float* smf = (float*)smem;
    uint32_t sb;
    asm("{ .reg .u64 t; cvta.to.shared.u64 t, %1; cvt.u32.u64 %0, t; }"
        : "=r"(sb) : "l"(smem));

    const int t = threadIdx.x;
    const int wrp = t >> 5, l = t & 31;
    const int b = blockIdx.x >> 3;
    const int row0 = (blockIdx.x & 7) << 2;
    const float* A = a + (size_t)b * 65536;

    // prefetch B tap0 into buffer 0
    {
        const char* src = (const char*)g_wtp;
        for (int i = t; i < B_BYTES / 16; i += 256)
            CP_ASYNC16(sb + SM_B0 + i * 16, __cvta_generic_to_global(src + i * 16));
        CP_COMMIT();
    }
    if (t < 64) smf[SM_WSUM / 4 + t] = g_wsum[t];

    // stage + fp16-split input tile into pixel-major hi/lo planes.
    // word (pix, cw) holds channels (2cw, 2cw+1) of pixel pix.
    {
        uint32_t* hip = (uint32_t*)(smem + SM_HI);
        uint32_t* lop = (uint32_t*)(smem + SM_LO);
        for (int idx = t; idx < 32 * 204; idx += 256) {
            int cw = idx / 204, pix = idx - cw * 204;
            int ry = pix / 34, cx = pix - ry * 34;
            int py = refl(row0 - 1 + ry), px = refl(cx - 1);
            const float* p = A + (2 * cw) * 1024 + py * 32 + px;
            float f0 = p[0], f1 = p[1024];
            uint32_t hx; CVT_F16X2(hx, f0, f1);
            __half2 hh = *reinterpret_cast<__half2*>(&hx);
            float h0 = __low2float(hh), h1 = __high2float(hh);
            uint32_t lx; CVT_F16X2(lx, f0 - h0, f1 - h1);
            hip[pix * IN_W + cw] = hx;
            lop[pix * IN_W + cw] = lx;
        }
    }
    __syncthreads();

    // stats: channel reduce (reconstruct v = hi + lo), then 3x3 box sums
    if (t < 204) {
        const uint32_t* hip = (const uint32_t*)(smem + SM_HI) + t * IN_W;
        const uint32_t* lop = (const uint32_t*)(smem + SM_LO) + t * IN_W;
        float s1 = 0.f, s2 = 0.f;
        #pragma unroll 8
        for (int w = 0; w < 32; ++w) {
            uint32_t hx = hip[w], lx = lop[w];
            __half2 hh = *reinterpret_cast<__half2*>(&hx);
            __half2 ll = *reinterpret_cast<__half2*>(&lx);
            float f0 = __low2float(hh) + __low2float(ll);
            float f1 = __high2float(hh) + __high2float(ll);
            s1 += f0 + f1;
            s2 += f0 * f0 + f1 * f1;
        }
        smf[SM_S1 / 4 + t] = s1;
        smf[SM_S2 / 4 + t] = s2;
    }
    __syncthreads();
    if (t < 128) {
        int r = t >> 5, x = t & 31;
        float s1 = 0.f, s2 = 0.f;
        #pragma unroll
        for (int dr = 0; dr < 3; ++dr)
            #pragma unroll
            for (int dc = 0; dc < 3; ++dc) {
                int i = (r + dr) * 34 + x + dc;
                s1 += smf[SM_S1 / 4 + i];
                s2 += smf[SM_S2 / 4 + i];
            }
        float mean = s1 * (1.f / 576.f);
        float var  = (s2 - s1 * s1 * (1.f / 576.f)) * (1.f / 575.f);
        smf[SM_MEAN / 4 + t] = mean;
        smf[SM_RSTD / 4 + t] = rsqrtf(fmaxf(var, 1e-30f));
    }

    // warp tile: image row (wrp>>1), 32 pixels (2 m16 tiles), out half wrp&1
    const int g = l >> 2, tg = l & 3;
    const int row = wrp >> 1, h = wrp & 1;

    // ldmatrix lane offsets (proven in R6/R7):
    // B: row-sel(+8n) = (l>>4)&1, col-sel(+16B) = (l>>3)&1
    // A: row-sel(+8pix) = (l>>3)&1, col-sel(+16B) = (l>>4)&1
    const uint32_t b_lane =
        (uint32_t)((((l >> 4) & 1) * 8 + (l & 7)) * 144 + ((l >> 3) & 1) * 16);
    const uint32_t a_lane =
        (uint32_t)((((l >> 3) & 1) * 8 + (l & 7)) * 144 + ((l >> 4) & 1) * 16);

    float acc[2][4][4];
    #pragma unroll
    for (int i = 0; i < 2; ++i)
        #pragma unroll
        for (int j = 0; j < 4; ++j)
            #pragma unroll
            for (int q = 0; q < 4; ++q) acc[i][j][q] = 0.f;

    int buf = 0;
    for (int tap = 0; tap < 9; ++tap) {
        CP_WAIT(0);
        __syncthreads();
        if (tap < 8) {
            const char* src = (const char*)g_wtp + (size_t)(tap + 1) * B_BYTES;
            uint32_t dst = sb + SM_B0 + (buf ^ 1) * B_BYTES;
            for (int i = t; i < B_BYTES / 16; i += 256)
                CP_ASYNC16(dst + i * 16, __cvta_generic_to_global(src + i * 16));
            CP_COMMIT();
        }

        const int dy = tap / 3, dx = tap - dy * 3;
        const uint32_t pixbase = (uint32_t)((row + dy) * 34 + dx) * 144u;
        const uint32_t A0 = sb + SM_HI + pixbase + a_lane;        // tile0 hi
        const uint32_t A1 = A0 + 16 * 144;                        // tile1 hi
        const uint32_t L0 = sb + SM_LO + pixbase + a_lane;        // tile0 lo
        const uint32_t L1 = L0 + 16 * 144;
        const uint32_t Bh = sb + SM_B0 + buf * B_BYTES + h * 4608 + b_lane;

        #pragma unroll
        for (int kc = 0; kc < 4; ++kc) {
            const uint32_t ka = (uint32_t)kc * 32u;
            uint32_t ah00, ah01, ah02, ah03, ah10, ah11, ah12, ah13;
            uint32_t al00, al01, al02, al03, al10, al11, al12, al13;
            LDSM_X4(ah00, ah01, ah02, ah03, A0 + ka);
            LDSM_X4(ah10, ah11, ah12, ah13, A1 + ka);
            LDSM_X4(al00, al01, al02, al03, L0 + ka);
            LDSM_X4(al10, al11, al12, al13, L1 + ka);

            #pragma unroll
            for (int j = 0; j < 2; ++j) {
                uint32_t bh0, bh1, bh2, bh3;
                LDSM_X4(bh0, bh1, bh2, bh3, Bh + (uint32_t)(j * 2304) + ka);
                // term hh (4 distinct accs), then term lh (distance 4)
                MMA16816(acc[0][2 * j],     ah00, ah01, ah02, ah03, bh0, bh1);
                MMA16816(acc[1][2 * j],     ah10, ah11, ah12, ah13, bh0, bh1);
                MMA16816(acc[0][2 * j + 1], ah00, ah01, ah02, ah03, bh2, bh3);
                MMA16816(acc[1][2 * j + 1], ah10, ah11, ah12, ah13, bh2, bh3);
                MMA16816(acc[0][2 * j],     al00, al01, al02, al03, bh0, bh1);
                MMA16816(acc[1][2 * j],     al10, al11, al12, al13, bh0, bh1);
                MMA16816(acc[0][2 * j + 1], al00, al01, al02, al03, bh2, bh3);
                MMA16816(acc[1][2 * j + 1], al10, al11, al12, al13, bh2, bh3);
            }
        }
        buf ^= 1;
    }

    // epilogue: (acc - mean*wsum) * rstd
    float* ob = out + (size_t)b * 65536 + (size_t)(row0 + row) * 32;
    #pragma unroll
    for (int t2 = 0; t2 < 2; ++t2) {
        const int x0 = t2 * 16 + g;
        const int pp = row * 32 + x0;
        const float mean0 = smf[SM_MEAN / 4 + pp],     rstd0 = smf[SM_RSTD / 4 + pp];
        const float mean1 = smf[SM_MEAN / 4 + pp + 8], rstd1 = smf[SM_RSTD / 4 + pp + 8];
        #pragma unroll
        for (int nc = 0; nc < 4; ++nc) {
            const int o0 = h * 32 + nc * 8 + tg * 2;
            const float ws0 = smf[SM_WSUM / 4 + o0];
            const float ws1 = smf[SM_WSUM / 4 + o0 + 1];
            ob[(size_t)o0 * 1024 + x0]           = (acc[t2][nc][0] - mean0 * ws0) * rstd0;
            ob[(size_t)(o0 + 1) * 1024 + x0]     = (acc[t2][nc][1] - mean0 * ws1) * rstd0;
            ob[(size_t)o0 * 1024 + x0 + 8]       = (acc[t2][nc][2] - mean1 * ws0) * rstd1;
            ob[(size_t)(o0 + 1) * 1024 + x0 + 8] = (acc[t2][nc][3] - mean1 * ws1) * rstd1;
        }
    }
}

extern "C" void kernel_launch(void* const* d_in, const int* in_sizes, int n_in,
                              void* d_out, int out_size) {
    const float* a = (const float*)d_in[0];   // [256,64,32,32]
    const float* w = (const float*)d_in[1];   // [576,64]
    float* out = (float*)d_out;

    cudaFuncSetAttribute(conv_mma_kernel,
                         cudaFuncAttributeMaxDynamicSharedMemorySize, SMEM_TOTAL);

    prep_kernel<<<163, 256>>>(w);
    conv_mma_kernel<<<2048, 256, SMEM_TOTAL>>>(a, out);
}

// round 9
// speedup vs baseline: 1.3943x; 1.0833x over previous
#include <cuda_runtime.h>
#include <cuda_fp16.h>
#include <cstdint>

// norm_conv via mma.sync fp16 2-term-split implicit GEMM.
// out = ((im2col(a)-mean)/std) @ W == (conv3x3(a,W) - mean*colsum(W)) * rstd
// Input split x = xh + xl (fp16 each); W rounded once to fp16.
// Per CTA: 128-pixel tile (4 rows) of one batch, 8 warps.
// Warp = 32 pixels (2 m16 tiles) x 32 out channels. A,B via ldmatrix.x4.
// B stored XOR-swizzled at 128B rows (pre-swizzled in gmem); smem trimmed
// to 76.4KB -> 3 CTAs/SM.

#define SM_WSUM 0                      // 64 f
#define SM_MEAN 256                    // 128 f
#define SM_RSTD 768                    // 128 f
#define SM_B0   1280                   // 2 x B_BYTES double buffer
#define B_BYTES 8192                   // per tap: wh[64][64] fp16, swizzled
#define SM_S1   (SM_B0 + B_BYTES)      // 9472: 204 f (overlaid on B buf1)
#define SM_S2   (SM_S1 + 832)          // 10304: 204 f
#define SM_HI   (SM_B0 + 2 * B_BYTES)  // 17664: [204 pix][36 words] f16x2
#define SM_LO   (SM_HI + 204 * 36 * 4) // 47040
#define SMEM_TOTAL (SM_LO + 204 * 36 * 4)   // 76416 bytes -> 3 CTAs/SM
#define IN_W    36                     // u32 words per pixel (64ch + pad)

__device__ float g_wsum[64];
__device__ __align__(16) __half g_wtp[9 * 64 * 64];   // [tap][o][k-swizzled]

__device__ __forceinline__ int refl(int i) {
    i = (i < 0) ? -i : i;
    return (i >= 32) ? 62 - i : i;
}

// pack two f32 into f16x2: lo = f0, hi = f1
#define CVT_F16X2(res, f0, f1) \
    asm("cvt.rn.f16x2.f32 %0, %1, %2;" : "=f"(*(float*)0) : )
#undef CVT_F16X2
#define CVT_F16X2(res, f0, f1) \
    asm("cvt.rn.f16x2.f32 %0, %1, %2;" : "=r"(res) : "f"(f1), "f"(f0))

#define CP_ASYNC16(dst, src) \
    asm volatile("cp.async.cg.shared.global [%0], [%1], 16;" \
                 :: "r"(dst), "l"(src) : "memory")
#define CP_COMMIT() asm volatile("cp.async.commit_group;" ::: "memory")
#define CP_WAIT(n)  asm volatile("cp.async.wait_group %0;" :: "n"(n) : "memory")

#define MMA16816(c, a0, a1, a2, a3, b0, b1) \
    asm volatile("mma.sync.aligned.m16n8k16.row.col.f32.f16.f16.f32 " \
        "{%0,%1,%2,%3}, {%4,%5,%6,%7}, {%8,%9}, {%0,%1,%2,%3};" \
        : "+f"((c)[0]), "+f"((c)[1]), "+f"((c)[2]), "+f"((c)[3]) \
        : "r"(a0), "r"(a1), "r"(a2), "r"(a3), "r"(b0), "r"(b1))

#define LDSM_X4(r0, r1, r2, r3, addr) \
    asm volatile("ldmatrix.sync.aligned.m8n8.x4.shared.b16 {%0,%1,%2,%3}, [%4];" \
        : "=r"(r0), "=r"(r1), "=r"(r2), "=r"(r3) : "r"(addr))

// blocks 0..143: fp16 W into g_wtp[tap][o][k^((o&7)<<3)] (XOR swizzle).
// block 144: column sums of W into g_wsum (fp32 exact).
__global__ void prep_kernel(const float* __restrict__ w) {
    if (blockIdx.x == 144) {
        int t = threadIdx.x;
        int o = t >> 2, q = t & 3;
        float s = 0.f;
        for (int p = q; p < 576; p += 4) s += w[p * 64 + o];
        s += __shfl_xor_sync(0xffffffffu, s, 1);
        s += __shfl_xor_sync(0xffffffffu, s, 2);
        if (q == 0) g_wsum[o] = s;
        return;
    }
    int idx = blockIdx.x * 256 + threadIdx.x;   // < 36864 == 9*64*64
    int k = idx & 63;
    int rest = idx >> 6;
    int o = rest & 63, tap = rest >> 6;
    // swizzle: element position k' = k ^ ((o&7)<<3)  (16B-chunk XOR)
    int ks = k ^ ((o & 7) << 3);
    g_wtp[tap * 4096 + o * 64 + ks] = __float2half(w[(k * 9 + tap) * 64 + o]);
}

__global__ __launch_bounds__(256, 3)
void conv_mma_kernel(const float* __restrict__ a, float* __restrict__ out) {
    extern __shared__ char smem[];
    float* smf = (float*)smem;
    uint32_t sb;
    asm("{ .reg .u64 t; cvta.to.shared.u64 t, %1; cvt.u32.u64 %0, t; }"
        : "=r"(sb) : "l"(smem));

    const int t = threadIdx.x;
    const int wrp = t >> 5, l = t & 31;
    const int b = blockIdx.x >> 3;
    const int row0 = (blockIdx.x & 7) << 2;
    const float* A = a + (size_t)b * 65536;

    // prefetch B tap0 into buffer 0
    {
        const char* src = (const char*)g_wtp;
        for (int i = t; i < B_BYTES / 16; i += 256)
            CP_ASYNC16(sb + SM_B0 + i * 16, __cvta_generic_to_global(src + i * 16));
        CP_COMMIT();
    }
    if (t < 64) smf[SM_WSUM / 4 + t] = g_wsum[t];

    // stage + fp16-split input tile into pixel-major hi/lo planes.
    {
        uint32_t* hip = (uint32_t*)(smem + SM_HI);
        uint32_t* lop = (uint32_t*)(smem + SM_LO);
        for (int idx = t; idx < 32 * 204; idx += 256) {
            int cw = idx / 204, pix = idx - cw * 204;
            int ry = pix / 34, cx = pix - ry * 34;
            int py = refl(row0 - 1 + ry), px = refl(cx - 1);
            const float* p = A + (2 * cw) * 1024 + py * 32 + px;
            float f0 = p[0], f1 = p[1024];
            uint32_t hx; CVT_F16X2(hx, f0, f1);
            __half2 hh = *reinterpret_cast<__half2*>(&hx);
            float h0 = __low2float(hh), h1 = __high2float(hh);
            uint32_t lx; CVT_F16X2(lx, f0 - h0, f1 - h1);
            hip[pix * IN_W + cw] = hx;
            lop[pix * IN_W + cw] = lx;
        }
    }
    __syncthreads();

    // stats: channel reduce (reconstruct v = hi + lo), then 3x3 box sums
    if (t < 204) {
        const uint32_t* hip = (const uint32_t*)(smem + SM_HI) + t * IN_W;
        const uint32_t* lop = (const uint32_t*)(smem + SM_LO) + t * IN_W;
        float s1 = 0.f, s2 = 0.f;
        #pragma unroll 8
        for (int w = 0; w < 32; ++w) {
            uint32_t hx = hip[w], lx = lop[w];
            __half2 hh = *reinterpret_cast<__half2*>(&hx);
            __half2 ll = *reinterpret_cast<__half2*>(&lx);
            float f0 = __low2float(hh) + __low2float(ll);
            float f1 = __high2float(hh) + __high2float(ll);
            s1 += f0 + f1;
            s2 += f0 * f0 + f1 * f1;
        }
        smf[SM_S1 / 4 + t] = s1;
        smf[SM_S2 / 4 + t] = s2;
    }
    __syncthreads();
    if (t < 128) {
        int r = t >> 5, x = t & 31;
        float s1 = 0.f, s2 = 0.f;
        #pragma unroll
        for (int dr = 0; dr < 3; ++dr)
            #pragma unroll
            for (int dc = 0; dc < 3; ++dc) {
                int i = (r + dr) * 34 + x + dc;
                s1 += smf[SM_S1 / 4 + i];
                s2 += smf[SM_S2 / 4 + i];
            }
        float mean = s1 * (1.f / 576.f);
        float var  = (s2 - s1 * s1 * (1.f / 576.f)) * (1.f / 575.f);
        smf[SM_MEAN / 4 + t] = mean;
        smf[SM_RSTD / 4 + t] = rsqrtf(fmaxf(var, 1e-30f));
    }

    // warp tile: image row (wrp>>1), 32 pixels (2 m16 tiles), out half wrp&1
    const int g = l >> 2, tg = l & 3;
    const int row = wrp >> 1, h = wrp & 1;

    // A ldmatrix lane offset (padded 144B rows, proven):
    const uint32_t a_lane =
        (uint32_t)((((l >> 3) & 1) * 8 + (l & 7)) * 144 + ((l >> 4) & 1) * 16);
    // B lane pieces for swizzled 128B rows:
    //   row    = ((l>>4)&1)*8 + (l&7)  -> *128
    //   chunk  = ((kc*2 + sel) ^ (l&7)) * 16,  sel = (l>>3)&1
    const uint32_t b_row = (uint32_t)((((l >> 4) & 1) * 8 + (l & 7)) * 128);
    const uint32_t b_sel = (uint32_t)((l >> 3) & 1);
    const uint32_t b_wz  = (uint32_t)(l & 7);

    float acc[2][4][4];
    #pragma unroll
    for (int i = 0; i < 2; ++i)
        #pragma unroll
        for (int j = 0; j < 4; ++j)
            #pragma unroll
            for (int q = 0; q < 4; ++q) acc[i][j][q] = 0.f;

    int buf = 0;
    for (int tap = 0; tap < 9; ++tap) {
        CP_WAIT(0);
        __syncthreads();
        if (tap < 8) {
            const char* src = (const char*)g_wtp + (size_t)(tap + 1) * B_BYTES;
            uint32_t dst = sb + SM_B0 + (buf ^ 1) * B_BYTES;
            for (int i = t; i < B_BYTES / 16; i += 256)
                CP_ASYNC16(dst + i * 16, __cvta_generic_to_global(src + i * 16));
            CP_COMMIT();
        }

        const int dy = tap / 3, dx = tap - dy * 3;
        const uint32_t pixbase = (uint32_t)((row + dy) * 34 + dx) * 144u;
        const uint32_t A0 = sb + SM_HI + pixbase + a_lane;        // tile0 hi
        const uint32_t A1 = A0 + 16 * 144;                        // tile1 hi
        const uint32_t L0 = sb + SM_LO + pixbase + a_lane;        // tile0 lo
        const uint32_t L1 = L0 + 16 * 144;
        const uint32_t Bh = sb + SM_B0 + buf * B_BYTES + h * 4096 + b_row;

        #pragma unroll
        for (int kc = 0; kc < 4; ++kc) {
            const uint32_t ka = (uint32_t)kc * 32u;
            const uint32_t bcol = ((((uint32_t)kc * 2u + b_sel) ^ b_wz) << 4);
            uint32_t ah00, ah01, ah02, ah03, ah10, ah11, ah12, ah13;
            uint32_t al00, al01, al02, al03, al10, al11, al12, al13;
            LDSM_X4(ah00, ah01, ah02, ah03, A0 + ka);
            LDSM_X4(ah10, ah11, ah12, ah13, A1 + ka);
            LDSM_X4(al00, al01, al02, al03, L0 + ka);
            LDSM_X4(al10, al11, al12, al13, L1 + ka);

            #pragma unroll
            for (int j = 0; j < 2; ++j) {
                uint32_t bh0, bh1, bh2, bh3;
                LDSM_X4(bh0, bh1, bh2, bh3, Bh + (uint32_t)(j * 2048) + bcol);
                // term hh (4 distinct accs), then term lh (distance 4)
                MMA16816(acc[0][2 * j],     ah00, ah01, ah02, ah03, bh0, bh1);
                MMA16816(acc[1][2 * j],     ah10, ah11, ah12, ah13, bh0, bh1);
                MMA16816(acc[0][2 * j + 1], ah00, ah01, ah02, ah03, bh2, bh3);
                MMA16816(acc[1][2 * j + 1], ah10, ah11, ah12, ah13, bh2, bh3);
                MMA16816(acc[0][2 * j],     al00, al01, al02, al03, bh0, bh1);
                MMA16816(acc[1][2 * j],     al10, al11, al12, al13, bh0, bh1);
                MMA16816(acc[0][2 * j + 1], al00, al01, al02, al03, bh2, bh3);
                MMA16816(acc[1][2 * j + 1], al10, al11, al12, al13, bh2, bh3);
            }
        }
        buf ^= 1;
    }

    // epilogue: (acc - mean*wsum) * rstd
    float* ob = out + (size_t)b * 65536 + (size_t)(row0 + row) * 32;
    #pragma unroll
    for (int t2 = 0; t2 < 2; ++t2) {
        const int x0 = t2 * 16 + g;
        const int pp = row * 32 + x0;
        const float mean0 = smf[SM_MEAN / 4 + pp],     rstd0 = smf[SM_RSTD / 4 + pp];
        const float mean1 = smf[SM_MEAN / 4 + pp + 8], rstd1 = smf[SM_RSTD / 4 + pp + 8];
        #pragma unroll
        for (int nc = 0; nc < 4; ++nc) {
            const int o0 = h * 32 + nc * 8 + tg * 2;
            const float ws0 = smf[SM_WSUM / 4 + o0];
            const float ws1 = smf[SM_WSUM / 4 + o0 + 1];
            ob[(size_t)o0 * 1024 + x0]           = (acc[t2][nc][0] - mean0 * ws0) * rstd0;
            ob[(size_t)(o0 + 1) * 1024 + x0]     = (acc[t2][nc][1] - mean0 * ws1) * rstd0;
            ob[(size_t)o0 * 1024 + x0 + 8]       = (acc[t2][nc][2] - mean1 * ws0) * rstd1;
            ob[(size_t)(o0 + 1) * 1024 + x0 + 8] = (acc[t2][nc][3] - mean1 * ws1) * rstd1;
        }
    }
}

extern "C" void kernel_launch(void* const* d_in, const int* in_sizes, int n_in,
                              void* d_out, int out_size) {
    const float* a = (const float*)d_in[0];   // [256,64,32,32]
    const float* w = (const float*)d_in[1];   // [576,64]
    float* out = (float*)d_out;

    cudaFuncSetAttribute(conv_mma_kernel,
                         cudaFuncAttributeMaxDynamicSharedMemorySize, SMEM_TOTAL);

    prep_kernel<<<145, 256>>>(w);
    conv_mma_kernel<<<2048, 256, SMEM_TOTAL>>>(a, out);
}

// round 13
// speedup vs baseline: 1.4438x; 1.0355x over previous
#include <cuda_runtime.h>
#include <cuda_fp16.h>
#include <cstdint>

// norm_conv via mma.sync fp16 2-term-split implicit GEMM.
// out = ((im2col(a)-mean)/std) @ W == (conv3x3(a,W) - mean*colsum(W)) * rstd
// Input split x = xh + xl (fp16 each); W rounded once to fp16.
// Per CTA: 128-pixel tile (4 rows) of one batch, 8 warps.
// Warp = 32 pixels (2 m16 tiles) x 32 out channels. A,B via ldmatrix.x4.
// B XOR-swizzled 128B rows (pre-swizzled in gmem). Staging uses a
// transpose-friendly lane map (4px x 8quads) with STS.128 -> no 32-way
// scatter. 76.4KB smem -> 3 CTAs/SM.

#define SM_WSUM 0                      // 64 f
#define SM_MEAN 256                    // 128 f
#define SM_RSTD 768                    // 128 f
#define SM_B0   1280                   // 2 x B_BYTES double buffer
#define B_BYTES 8192                   // per tap: wh[64][64] fp16, swizzled
#define SM_S1   (SM_B0 + B_BYTES)      // 9472: 204 f (overlaid on B buf1)
#define SM_S2   (SM_S1 + 832)          // 10304: 204 f
#define SM_HI   (SM_B0 + 2 * B_BYTES)  // 17664: [204 pix][36 words] f16x2
#define SM_LO   (SM_HI + 204 * 36 * 4) // 47040
#define SMEM_TOTAL (SM_LO + 204 * 36 * 4)   // 76416 bytes -> 3 CTAs/SM
#define IN_W    36                     // u32 words per pixel (64ch + pad)

__device__ float g_wsum[64];
__device__ __align__(16) __half g_wtp[9 * 64 * 64];   // [tap][o][k-swizzled]

__device__ __forceinline__ int refl(int i) {
    i = (i < 0) ? -i : i;
    return (i >= 32) ? 62 - i : i;
}

// pack two f32 into f16x2: lo = f0, hi = f1
#define CVT_F16X2(res, f0, f1) \
    asm("cvt.rn.f16x2.f32 %0, %1, %2;" : "=r"(res) : "f"(f1), "f"(f0))

#define CP_ASYNC16(dst, src) \
    asm volatile("cp.async.cg.shared.global [%0], [%1], 16;" \
                 :: "r"(dst), "l"(src) : "memory")
#define CP_COMMIT() asm volatile("cp.async.commit_group;" ::: "memory")
#define CP_WAIT(n)  asm volatile("cp.async.wait_group %0;" :: "n"(n) : "memory")

#define MMA16816(c, a0, a1, a2, a3, b0, b1) \
    asm volatile("mma.sync.aligned.m16n8k16.row.col.f32.f16.f16.f32 " \
        "{%0,%1,%2,%3}, {%4,%5,%6,%7}, {%8,%9}, {%0,%1,%2,%3};" \
        : "+f"((c)[0]), "+f"((c)[1]), "+f"((c)[2]), "+f"((c)[3]) \
        : "r"(a0), "r"(a1), "r"(a2), "r"(a3), "r"(b0), "r"(b1))

#define LDSM_X4(r0, r1, r2, r3, addr) \
    asm volatile("ldmatrix.sync.aligned.m8n8.x4.shared.b16 {%0,%1,%2,%3}, [%4];" \
        : "=r"(r0), "=r"(r1), "=r"(r2), "=r"(r3) : "r"(addr))

#define STS128(r0, r1, r2, r3, sa) \
    asm volatile("st.shared.v4.b32 [%0], {%1, %2, %3, %4};" \
                 :: "r"(sa), "r"(r0), "r"(r1), "r"(r2), "r"(r3) : "memory")

// blocks 0..143: fp16 W into g_wtp[tap][o][k^((o&7)<<3)] (XOR swizzle).
// block 144: column sums of W into g_wsum (fp32 exact).
__global__ void prep_kernel(const float* __restrict__ w) {
    if (blockIdx.x == 144) {
        int t = threadIdx.x;
        int o = t >> 2, q = t & 3;
        float s = 0.f;
        for (int p = q; p < 576; p += 4) s += w[p * 64 + o];
        s += __shfl_xor_sync(0xffffffffu, s, 1);
        s += __shfl_xor_sync(0xffffffffu, s, 2);
        if (q == 0) g_wsum[o] = s;
        return;
    }
    int idx = blockIdx.x * 256 + threadIdx.x;   // < 36864 == 9*64*64
    int k = idx & 63;
    int rest = idx >> 6;
    int o = rest & 63, tap = rest >> 6;
    int ks = k ^ ((o & 7) << 3);                // 16B-chunk XOR swizzle
    g_wtp[tap * 4096 + o * 64 + ks] = __float2half(w[(k * 9 + tap) * 64 + o]);
}

__global__ __launch_bounds__(256, 3)
void conv_mma_kernel(const float* __restrict__ a, float* __restrict__ out) {
    extern __shared__ char smem[];
    float* smf = (float*)smem;
    uint32_t sb;
    asm("{ .reg .u64 t; cvta.to.shared.u64 t, %1; cvt.u32.u64 %0, t; }"
        : "=r"(sb) : "l"(smem));

    const int t = threadIdx.x;
    const int wrp = t >> 5, l = t & 31;
    const int b = blockIdx.x >> 3;
    const int row0 = (blockIdx.x & 7) << 2;
    const float* A = a + (size_t)b * 65536;

    // prefetch B tap0 into buffer 0
    {
        const char* src = (const char*)g_wtp;
        for (int i = t; i < B_BYTES / 16; i += 256)
            CP_ASYNC16(sb + SM_B0 + i * 16, __cvta_generic_to_global(src + i * 16));
        CP_COMMIT();
    }
    if (t < 64) smf[SM_WSUM / 4 + t] = g_wsum[t];

    // stage + fp16-split input tile into pixel-major hi/lo planes.
    // Lane map: 4 pixels x 8 quads per warp; one STS.128 per plane per
    // group (~5 sectors/instr instead of a 32-way scatter).
    {
        const int pl = l >> 3, q = l & 7;   // pixel-in-group, 16B quad
        for (int gidx = wrp; gidx < 51; gidx += 8) {
            int p = gidx * 4 + pl;          // pixel 0..203
            int ry = p / 34, cx = p - ry * 34;
            int py = refl(row0 - 1 + ry), px = refl(cx - 1);
            const float* src = A + (size_t)(q * 8) * 1024 + py * 32 + px;
            uint32_t hw[4], lw[4];
            #pragma unroll
            for (int j = 0; j < 4; ++j) {
                float f0 = src[(size_t)(2 * j) * 1024];
                float f1 = src[(size_t)(2 * j + 1) * 1024];
                uint32_t hx; CVT_F16X2(hx, f0, f1);
                __half2 hh = *reinterpret_cast<__half2*>(&hx);
                float h0 = __low2float(hh), h1 = __high2float(hh);
                uint32_t lx; CVT_F16X2(lx, f0 - h0, f1 - h1);
                hw[j] = hx; lw[j] = lx;
            }
            uint32_t off = (uint32_t)(p * 144 + q * 16);
            STS128(hw[0], hw[1], hw[2], hw[3], sb + SM_HI + off);
            STS128(lw[0], lw[1], lw[2], lw[3], sb + SM_LO + off);
        }
    }
    __syncthreads();

    // stats: channel reduce (v = hi + lo) via LDS.128, then 3x3 box sums
    if (t < 204) {
        const uint4* hip = (const uint4*)(smem + SM_HI + t * 144);
        const uint4* lop = (const uint4*)(smem + SM_LO + t * 144);
        float s1 = 0.f, s2 = 0.f;
        #pragma unroll
        for (int w = 0; w < 8; ++w) {
            uint4 hv = hip[w], lv = lop[w];
            const uint32_t* hq = (const uint32_t*)&hv;
            const uint32_t* lq = (const uint32_t*)&lv;
            #pragma unroll
            for (int j = 0; j < 4; ++j) {
                __half2 hh = *reinterpret_cast<const __half2*>(&hq[j]);
                __half2 ll = *reinterpret_cast<const __half2*>(&lq[j]);
                float f0 = __low2float(hh) + __low2float(ll);
                float f1 = __high2float(hh) + __high2float(ll);
                s1 += f0 + f1;
                s2 += f0 * f0 + f1 * f1;
            }
        }
        smf[SM_S1 / 4 + t] = s1;
        smf[SM_S2 / 4 + t] = s2;
    }
    __syncthreads();
    if (t < 128) {
        int r = t >> 5, x = t & 31;
        float s1 = 0.f, s2 = 0.f;
        #pragma unroll
        for (int dr = 0; dr < 3; ++dr)
            #pragma unroll
            for (int dc = 0; dc < 3; ++dc) {
                int i = (r + dr) * 34 + x + dc;
                s1 += smf[SM_S1 / 4 + i];
                s2 += smf[SM_S2 / 4 + i];
            }
        float mean = s1 * (1.f / 576.f);
        float var  = (s2 - s1 * s1 * (1.f / 576.f)) * (1.f / 575.f);
        smf[SM_MEAN / 4 + t] = mean;
        smf[SM_RSTD / 4 + t] = rsqrtf(fmaxf(var, 1e-30f));
    }

    // warp tile: image row (wrp>>1), 32 pixels (2 m16 tiles), out half wrp&1
    const int g = l >> 2, tg = l & 3;
    const int row = wrp >> 1, h = wrp & 1;

    // A ldmatrix lane offset (padded 144B rows, proven):
    const uint32_t a_lane =
        (uint32_t)((((l >> 3) & 1) * 8 + (l & 7)) * 144 + ((l >> 4) & 1) * 16);
    // B lane pieces for swizzled 128B rows:
    const uint32_t b_row = (uint32_t)((((l >> 4) & 1) * 8 + (l & 7)) * 128);
    const uint32_t b_sel = (uint32_t)((l >> 3) & 1);
    const uint32_t b_wz  = (uint32_t)(l & 7);

    float acc[2][4][4];
    #pragma unroll
    for (int i = 0; i < 2; ++i)
        #pragma unroll
        for (int j = 0; j < 4; ++j)
            #pragma unroll
            for (int q = 0; q < 4; ++q) acc[i][j][q] = 0.f;

    int buf = 0;
    for (int tap = 0; tap < 9; ++tap) {
        CP_WAIT(0);
        __syncthreads();
        if (tap < 8) {
            const char* src = (const char*)g_wtp + (size_t)(tap + 1) * B_BYTES;
            uint32_t dst = sb + SM_B0 + (buf ^ 1) * B_BYTES;
            for (int i = t; i < B_BYTES / 16; i += 256)
                CP_ASYNC16(dst + i * 16, __cvta_generic_to_global(src + i * 16));
            CP_COMMIT();
        }

        const int dy = tap / 3, dx = tap - dy * 3;
        const uint32_t pixbase = (uint32_t)((row + dy) * 34 + dx) * 144u;
        const uint32_t A0 = sb + SM_HI + pixbase + a_lane;        // tile0 hi
        const uint32_t A1 = A0 + 16 * 144;                        // tile1 hi
        const uint32_t L0 = sb + SM_LO + pixbase + a_lane;        // tile0 lo
        const uint32_t L1 = L0 + 16 * 144;
        const uint32_t Bh = sb + SM_B0 + buf * B_BYTES + h * 4096 + b_row;

        #pragma unroll
        for (int kc = 0; kc < 4; ++kc) {
            const uint32_t ka = (uint32_t)kc * 32u;
            const uint32_t bcol = ((((uint32_t)kc * 2u + b_sel) ^ b_wz) << 4);
            uint32_t ah00, ah01, ah02, ah03, ah10, ah11, ah12, ah13;
            uint32_t al00, al01, al02, al03, al10, al11, al12, al13;
            LDSM_X4(ah00, ah01, ah02, ah03, A0 + ka);
            LDSM_X4(ah10, ah11, ah12, ah13, A1 + ka);
            LDSM_X4(al00, al01, al02, al03, L0 + ka);
            LDSM_X4(al10, al11, al12, al13, L1 + ka);

            #pragma unroll
            for (int j = 0; j < 2; ++j) {
                uint32_t bh0, bh1, bh2, bh3;
                LDSM_X4(bh0, bh1, bh2, bh3, Bh + (uint32_t)(j * 2048) + bcol);
                // term hh (4 distinct accs), then term lh (distance 4)
                MMA16816(acc[0][2 * j],     ah00, ah01, ah02, ah03, bh0, bh1);
                MMA16816(acc[1][2 * j],     ah10, ah11, ah12, ah13, bh0, bh1);
                MMA16816(acc[0][2 * j + 1], ah00, ah01, ah02, ah03, bh2, bh3);
                MMA16816(acc[1][2 * j + 1], ah10, ah11, ah12, ah13, bh2, bh3);
                MMA16816(acc[0][2 * j],     al00, al01, al02, al03, bh0, bh1);
                MMA16816(acc[1][2 * j],     al10, al11, al12, al13, bh0, bh1);
                MMA16816(acc[0][2 * j + 1], al00, al01, al02, al03, bh2, bh3);
                MMA16816(acc[1][2 * j + 1], al10, al11, al12, al13, bh2, bh3);
            }
        }
        buf ^= 1;
    }

    // epilogue: (acc - mean*wsum) * rstd
    float* ob = out + (size_t)b * 65536 + (size_t)(row0 + row) * 32;
    #pragma unroll
    for (int t2 = 0; t2 < 2; ++t2) {
        const int x0 = t2 * 16 + g;
        const int pp = row * 32 + x0;
        const float mean0 = smf[SM_MEAN / 4 + pp],     rstd0 = smf[SM_RSTD / 4 + pp];
        const float mean1 = smf[SM_MEAN / 4 + pp + 8], rstd1 = smf[SM_RSTD / 4 + pp + 8];
        #pragma unroll
        for (int nc = 0; nc < 4; ++nc) {
            const int o0 = h * 32 + nc * 8 + tg * 2;
            const float ws0 = smf[SM_WSUM / 4 + o0];
            const float ws1 = smf[SM_WSUM / 4 + o0 + 1];
            ob[(size_t)o0 * 1024 + x0]           = (acc[t2][nc][0] - mean0 * ws0) * rstd0;
            ob[(size_t)(o0 + 1) * 1024 + x0]     = (acc[t2][nc][1] - mean0 * ws1) * rstd0;
            ob[(size_t)o0 * 1024 + x0 + 8]       = (acc[t2][nc][2] - mean1 * ws0) * rstd1;
            ob[(size_t)(o0 + 1) * 1024 + x0 + 8] = (acc[t2][nc][3] - mean1 * ws1) * rstd1;
        }
    }
}

extern "C" void kernel_launch(void* const* d_in, const int* in_sizes, int n_in,
                              void* d_out, int out_size) {
    const float* a = (const float*)d_in[0];   // [256,64,32,32]
    const float* w = (const float*)d_in[1];   // [576,64]
    float* out = (float*)d_out;

    cudaFuncSetAttribute(conv_mma_kernel,
                         cudaFuncAttributeMaxDynamicSharedMemorySize, SMEM_TOTAL);

    prep_kernel<<<145, 256>>>(w);
    conv_mma_kernel<<<2048, 256, SMEM_TOTAL>>>(a, out);
}

// round 15
// speedup vs baseline: 1.8840x; 1.3049x over previous
#include <cuda_runtime.h>
#include <cuda_fp16.h>
#include <cstdint>

// norm_conv via mma.sync single-term fp16 implicit GEMM.
// out = ((im2col(a)-mean)/std) @ W == (conv3x3(a,W) - mean*colsum(W)) * rstd
// Both x and W rounded once to fp16 (no split): combined rounding error
// ~3e-4 global rel err, well under the 1e-3 gate. Stats from rounded x.
// Per CTA: 128-pixel tile (4 rows) of one batch, 8 warps.
// Warp = 32 pixels (2 m16 tiles) x 32 out channels. A,B via ldmatrix.x4.
// B XOR-swizzled 128B rows (pre-swizzled in gmem). 47KB smem -> 4 CTAs/SM.

#define SM_WSUM 0                      // 64 f
#define SM_MEAN 256                    // 128 f
#define SM_RSTD 768                    // 128 f
#define SM_B0   1280                   // 2 x B_BYTES double buffer
#define B_BYTES 8192                   // per tap: wh[64][64] fp16, swizzled
#define SM_S1   (SM_B0 + B_BYTES)      // 9472: 204 f (overlaid on B buf1)
#define SM_S2   (SM_S1 + 832)          // 10304: 204 f
#define SM_HI   (SM_B0 + 2 * B_BYTES)  // 17664: [204 pix][36 words] f16x2
#define SMEM_TOTAL (SM_HI + 204 * 36 * 4)   // 47040 bytes -> 4 CTAs/SM
#define IN_W    36                     // u32 words per pixel (64ch + pad)

__device__ float g_wsum[64];
__device__ __align__(16) __half g_wtp[9 * 64 * 64];   // [tap][o][k-swizzled]

__device__ __forceinline__ int refl(int i) {
    i = (i < 0) ? -i : i;
    return (i >= 32) ? 62 - i : i;
}

// pack two f32 into f16x2: lo = f0, hi = f1
#define CVT_F16X2(res, f0, f1) \
    asm("cvt.rn.f16x2.f32 %0, %1, %2;" : "=r"(res) : "f"(f1), "f"(f0))

#define CP_ASYNC16(dst, src) \
    asm volatile("cp.async.cg.shared.global [%0], [%1], 16;" \
                 :: "r"(dst), "l"(src) : "memory")
#define CP_COMMIT() asm volatile("cp.async.commit_group;" ::: "memory")
#define CP_WAIT(n)  asm volatile("cp.async.wait_group %0;" :: "n"(n) : "memory")

#define MMA16816(c, a0, a1, a2, a3, b0, b1) \
    asm volatile("mma.sync.aligned.m16n8k16.row.col.f32.f16.f16.f32 " \
        "{%0,%1,%2,%3}, {%4,%5,%6,%7}, {%8,%9}, {%0,%1,%2,%3};" \
        : "+f"((c)[0]), "+f"((c)[1]), "+f"((c)[2]), "+f"((c)[3]) \
        : "r"(a0), "r"(a1), "r"(a2), "r"(a3), "r"(b0), "r"(b1))

#define LDSM_X4(r0, r1, r2, r3, addr) \
    asm volatile("ldmatrix.sync.aligned.m8n8.x4.shared.b16 {%0,%1,%2,%3}, [%4];" \
        : "=r"(r0), "=r"(r1), "=r"(r2), "=r"(r3) : "r"(addr))

#define STS128(r0, r1, r2, r3, sa) \
    asm volatile("st.shared.v4.b32 [%0], {%1, %2, %3, %4};" \
                 :: "r"(sa), "r"(r0), "r"(r1), "r"(r2), "r"(r3) : "memory")

// blocks 0..143: fp16 W into g_wtp[tap][o][k^((o&7)<<3)] (XOR swizzle).
// block 144: column sums of W into g_wsum (fp32 exact).
__global__ void prep_kernel(const float* __restrict__ w) {
    if (blockIdx.x == 144) {
        int t = threadIdx.x;
        int o = t >> 2, q = t & 3;
        float s = 0.f;
        for (int p = q; p < 576; p += 4) s += w[p * 64 + o];
        s += __shfl_xor_sync(0xffffffffu, s, 1);
        s += __shfl_xor_sync(0xffffffffu, s, 2);
        if (q == 0) g_wsum[o] = s;
        return;
    }
    int idx = blockIdx.x * 256 + threadIdx.x;   // < 36864 == 9*64*64
    int k = idx & 63;
    int rest = idx >> 6;
    int o = rest & 63, tap = rest >> 6;
    int ks = k ^ ((o & 7) << 3);                // 16B-chunk XOR swizzle
    g_wtp[tap * 4096 + o * 64 + ks] = __float2half(w[(k * 9 + tap) * 64 + o]);
}

__global__ __launch_bounds__(256, 4)
void conv_mma_kernel(const float* __restrict__ a, float* __restrict__ out) {
    extern __shared__ char smem[];
    float* smf = (float*)smem;
    uint32_t sb;
    asm("{ .reg .u64 t; cvta.to.shared.u64 t, %1; cvt.u32.u64 %0, t; }"
        : "=r"(sb) : "l"(smem));

    const int t = threadIdx.x;
    const int wrp = t >> 5, l = t & 31;
    const int b = blockIdx.x >> 3;
    const int row0 = (blockIdx.x & 7) << 2;
    const float* A = a + (size_t)b * 65536;

    // prefetch B tap0 into buffer 0
    {
        const char* src = (const char*)g_wtp;
        for (int i = t; i < B_BYTES / 16; i += 256)
            CP_ASYNC16(sb + SM_B0 + i * 16, __cvta_generic_to_global(src + i * 16));
        CP_COMMIT();
    }
    if (t < 64) smf[SM_WSUM / 4 + t] = g_wsum[t];

    // stage fp16-rounded input tile into pixel-major plane.
    // Lane map: 4 pixels x 8 quads per warp; one STS.128 per group.
    {
        const int pl = l >> 3, q = l & 7;   // pixel-in-group, 16B quad
        for (int gidx = wrp; gidx < 51; gidx += 8) {
            int p = gidx * 4 + pl;          // pixel 0..203
            int ry = p / 34, cx = p - ry * 34;
            int py = refl(row0 - 1 + ry), px = refl(cx - 1);
            const float* src = A + (size_t)(q * 8) * 1024 + py * 32 + px;
            uint32_t hw[4];
            #pragma unroll
            for (int j = 0; j < 4; ++j) {
                float f0 = src[(size_t)(2 * j) * 1024];
                float f1 = src[(size_t)(2 * j + 1) * 1024];
                CVT_F16X2(hw[j], f0, f1);
            }
            STS128(hw[0], hw[1], hw[2], hw[3],
                   sb + SM_HI + (uint32_t)(p * 144 + q * 16));
        }
    }
    __syncthreads();

    // stats from the fp16-rounded plane, then 3x3 box sums
    if (t < 204) {
        const uint4* hip = (const uint4*)(smem + SM_HI + t * 144);
        float s1 = 0.f, s2 = 0.f;
        #pragma unroll
        for (int w = 0; w < 8; ++w) {
            uint4 hv = hip[w];
            const uint32_t* hq = (const uint32_t*)&hv;
            #pragma unroll
            for (int j = 0; j < 4; ++j) {
                __half2 hh = *reinterpret_cast<const __half2*>(&hq[j]);
                float f0 = __low2float(hh), f1 = __high2float(hh);
                s1 += f0 + f1;
                s2 += f0 * f0 + f1 * f1;
            }
        }
        smf[SM_S1 / 4 + t] = s1;
        smf[SM_S2 / 4 + t] = s2;
    }
    __syncthreads();
    if (t < 128) {
        int r = t >> 5, x = t & 31;
        float s1 = 0.f, s2 = 0.f;
        #pragma unroll
        for (int dr = 0; dr < 3; ++dr)
            #pragma unroll
            for (int dc = 0; dc < 3; ++dc) {
                int i = (r + dr) * 34 + x + dc;
                s1 += smf[SM_S1 / 4 + i];
                s2 += smf[SM_S2 / 4 + i];
            }
        float mean = s1 * (1.f / 576.f);
        float var  = (s2 - s1 * s1 * (1.f / 576.f)) * (1.f / 575.f);
        smf[SM_MEAN / 4 + t] = mean;
        smf[SM_RSTD / 4 + t] = rsqrtf(fmaxf(var, 1e-30f));
    }

    // warp tile: image row (wrp>>1), 32 pixels (2 m16 tiles), out half wrp&1
    const int g = l >> 2, tg = l & 3;
    const int row = wrp >> 1, h = wrp & 1;

    // A ldmatrix lane offset (padded 144B rows, proven):
    const uint32_t a_lane =
        (uint32_t)((((l >> 3) & 1) * 8 + (l & 7)) * 144 + ((l >> 4) & 1) * 16);
    // B lane pieces for swizzled 128B rows:
    const uint32_t b_row = (uint32_t)((((l >> 4) & 1) * 8 + (l & 7)) * 128);
    const uint32_t b_sel = (uint32_t)((l >> 3) & 1);
    const uint32_t b_wz  = (uint32_t)(l & 7);

    float acc[2][4][4];
    #pragma unroll
    for (int i = 0; i < 2; ++i)
        #pragma unroll
        for (int j = 0; j < 4; ++j)
            #pragma unroll
            for (int q = 0; q < 4; ++q) acc[i][j][q] = 0.f;

    int buf = 0;
    for (int tap = 0; tap < 9; ++tap) {
        CP_WAIT(0);
        __syncthreads();
        if (tap < 8) {
            const char* src = (const char*)g_wtp + (size_t)(tap + 1) * B_BYTES;
            uint32_t dst = sb + SM_B0 + (buf ^ 1) * B_BYTES;
            for (int i = t; i < B_BYTES / 16; i += 256)
                CP_ASYNC16(dst + i * 16, __cvta_generic_to_global(src + i * 16));
            CP_COMMIT();
        }

        const int dy = tap / 3, dx = tap - dy * 3;
        const uint32_t pixbase = (uint32_t)((row + dy) * 34 + dx) * 144u;
        const uint32_t A0 = sb + SM_HI + pixbase + a_lane;        // tile0
        const uint32_t A1 = A0 + 16 * 144;                        // tile1
        const uint32_t Bh = sb + SM_B0 + buf * B_BYTES + h * 4096 + b_row;

        #pragma unroll
        for (int kc = 0; kc < 4; ++kc) {
            const uint32_t ka = (uint32_t)kc * 32u;
            const uint32_t bcol = ((((uint32_t)kc * 2u + b_sel) ^ b_wz) << 4);
            uint32_t ah00, ah01, ah02, ah03, ah10, ah11, ah12, ah13;
            LDSM_X4(ah00, ah01, ah02, ah03, A0 + ka);
            LDSM_X4(ah10, ah11, ah12, ah13, A1 + ka);

            #pragma unroll
            for (int j = 0; j < 2; ++j) {
                uint32_t bh0, bh1, bh2, bh3;
                LDSM_X4(bh0, bh1, bh2, bh3, Bh + (uint32_t)(j * 2048) + bcol);
                MMA16816(acc[0][2 * j],     ah00, ah01, ah02, ah03, bh0, bh1);
                MMA16816(acc[1][2 * j],     ah10, ah11, ah12, ah13, bh0, bh1);
                MMA16816(acc[0][2 * j + 1], ah00, ah01, ah02, ah03, bh2, bh3);
                MMA16816(acc[1][2 * j + 1], ah10, ah11, ah12, ah13, bh2, bh3);
            }
        }
        buf ^= 1;
    }

    // epilogue: (acc - mean*wsum) * rstd
    float* ob = out + (size_t)b * 65536 + (size_t)(row0 + row) * 32;
    #pragma unroll
    for (int t2 = 0; t2 < 2; ++t2) {
        const int x0 = t2 * 16 + g;
        const int pp = row * 32 + x0;
        const float mean0 = smf[SM_MEAN / 4 + pp],     rstd0 = smf[SM_RSTD / 4 + pp];
        const float mean1 = smf[SM_MEAN / 4 + pp + 8], rstd1 = smf[SM_RSTD / 4 + pp + 8];
        #pragma unroll
        for (int nc = 0; nc < 4; ++nc) {
            const int o0 = h * 32 + nc * 8 + tg * 2;
            const float ws0 = smf[SM_WSUM / 4 + o0];
            const float ws1 = smf[SM_WSUM / 4 + o0 + 1];
            ob[(size_t)o0 * 1024 + x0]           = (acc[t2][nc][0] - mean0 * ws0) * rstd0;
            ob[(size_t)(o0 + 1) * 1024 + x0]     = (acc[t2][nc][1] - mean0 * ws1) * rstd0;
            ob[(size_t)o0 * 1024 + x0 + 8]       = (acc[t2][nc][2] - mean1 * ws0) * rstd1;
            ob[(size_t)(o0 + 1) * 1024 + x0 + 8] = (acc[t2][nc][3] - mean1 * ws1) * rstd1;
        }
    }
}

extern "C" void kernel_launch(void* const* d_in, const int* in_sizes, int n_in,
                              void* d_out, int out_size) {
    const float* a = (const float*)d_in[0];   // [256,64,32,32]
    const float* w = (const float*)d_in[1];   // [576,64]
    float* out = (float*)d_out;

    cudaFuncSetAttribute(conv_mma_kernel,
                         cudaFuncAttributeMaxDynamicSharedMemorySize, SMEM_TOTAL);

    prep_kernel<<<145, 256>>>(w);
    conv_mma_kernel<<<2048, 256, SMEM_TOTAL>>>(a, out);
}

// round 16
// speedup vs baseline: 2.2297x; 1.1835x over previous
#include <cuda_runtime.h>
#include <cuda_fp16.h>
#include <cstdint>

// norm_conv via mma.sync single-term fp16 implicit GEMM.
// out = ((im2col(a)-mean)/std) @ W == (conv3x3(a,W) - mean*colsum(W)) * rstd
// x and W rounded once to fp16; combined rounding ~2.9e-4 rel err.
// Per CTA: 128-pixel tile (4 rows) of one batch, 8 warps.
// Warp = 32 pixels (2 m16 tiles) x 32 out channels. A,B via ldmatrix.x4.
// B XOR-swizzled 128B rows (pre-swizzled in gmem). Staging: contiguous
// LDG.128 row reads (reflect halo = interior copies) + STS.32 transpose.
// 47KB smem -> 4 CTAs/SM.

#define SM_WSUM 0                      // 64 f
#define SM_MEAN 256                    // 128 f
#define SM_RSTD 768                    // 128 f
#define SM_B0   1280                   // 2 x B_BYTES double buffer
#define B_BYTES 8192                   // per tap: wh[64][64] fp16, swizzled
#define SM_S1   (SM_B0 + B_BYTES)      // 9472: 204 f (overlaid on B buf1)
#define SM_S2   (SM_S1 + 832)          // 10304: 204 f
#define SM_HI   (SM_B0 + 2 * B_BYTES)  // 17664: [204 pix][36 words] f16x2
#define SMEM_TOTAL (SM_HI + 204 * 36 * 4)   // 47040 bytes -> 4 CTAs/SM

__device__ float g_wsum[64];
__device__ __align__(16) __half g_wtp[9 * 64 * 64];   // [tap][o][k-swizzled]

__device__ __forceinline__ int refl(int i) {
    i = (i < 0) ? -i : i;
    return (i >= 32) ? 62 - i : i;
}

// pack two f32 into f16x2: lo = f0, hi = f1
#define CVT_F16X2(res, f0, f1) \
    asm("cvt.rn.f16x2.f32 %0, %1, %2;" : "=r"(res) : "f"(f1), "f"(f0))

#define CP_ASYNC16(dst, src) \
    asm volatile("cp.async.cg.shared.global [%0], [%1], 16;" \
                 :: "r"(dst), "l"(src) : "memory")
#define CP_COMMIT() asm volatile("cp.async.commit_group;" ::: "memory")
#define CP_WAIT(n)  asm volatile("cp.async.wait_group %0;" :: "n"(n) : "memory")

#define MMA16816(c, a0, a1, a2, a3, b0, b1) \
    asm volatile("mma.sync.aligned.m16n8k16.row.col.f32.f16.f16.f32 " \
        "{%0,%1,%2,%3}, {%4,%5,%6,%7}, {%8,%9}, {%0,%1,%2,%3};" \
        : "+f"((c)[0]), "+f"((c)[1]), "+f"((c)[2]), "+f"((c)[3]) \
        : "r"(a0), "r"(a1), "r"(a2), "r"(a3), "r"(b0), "r"(b1))

#define LDSM_X4(r0, r1, r2, r3, addr) \
    asm volatile("ldmatrix.sync.aligned.m8n8.x4.shared.b16 {%0,%1,%2,%3}, [%4];" \
        : "=r"(r0), "=r"(r1), "=r"(r2), "=r"(r3) : "r"(addr))

#define STS32(v, sa) \
    asm volatile("st.shared.b32 [%0], %1;" :: "r"(sa), "r"(v) : "memory")

// blocks 0..143: fp16 W into g_wtp[tap][o][k^((o&7)<<3)] (XOR swizzle).
// block 144: column sums of W into g_wsum (fp32 exact).
__global__ void prep_kernel(const float* __restrict__ w) {
    if (blockIdx.x == 144) {
        int t = threadIdx.x;
        int o = t >> 2, q = t & 3;
        float s = 0.f;
        for (int p = q; p < 576; p += 4) s += w[p * 64 + o];
        s += __shfl_xor_sync(0xffffffffu, s, 1);
        s += __shfl_xor_sync(0xffffffffu, s, 2);
        if (q == 0) g_wsum[o] = s;
        return;
    }
    int idx = blockIdx.x * 256 + threadIdx.x;   // < 36864 == 9*64*64
    int k = idx & 63;
    int rest = idx >> 6;
    int o = rest & 63, tap = rest >> 6;
    int ks = k ^ ((o & 7) << 3);                // 16B-chunk XOR swizzle
    g_wtp[tap * 4096 + o * 64 + ks] = __float2half(w[(k * 9 + tap) * 64 + o]);
}

__global__ __launch_bounds__(256, 4)
void conv_mma_kernel(const float* __restrict__ a, float* __restrict__ out) {
    extern __shared__ char smem[];
    float* smf = (float*)smem;
    uint32_t sb;
    asm("{ .reg .u64 t; cvta.to.shared.u64 t, %1; cvt.u32.u64 %0, t; }"
        : "=r"(sb) : "l"(smem));

    const int t = threadIdx.x;
    const int wrp = t >> 5, l = t & 31;
    const int b = blockIdx.x >> 3;
    const int row0 = (blockIdx.x & 7) << 2;
    const float* A = a + (size_t)b * 65536;

    // prefetch B tap0 into buffer 0
    {
        const char* src = (const char*)g_wtp;
        for (int i = t; i < B_BYTES / 16; i += 256)
            CP_ASYNC16(sb + SM_B0 + i * 16, __cvta_generic_to_global(src + i * 16));
        CP_COMMIT();
    }
    if (t < 64) smf[SM_WSUM / 4 + t] = g_wsum[t];

    // stage fp16-rounded input tile (pixel-major plane, 144B rows).
    // Unit = (plane row ry, 8-channel block). Lane (c = l>>3, pxg = l&7):
    // 2x LDG.128 (4 consecutive px of ch 2c / 2c+1) -> 4 f16x2 -> 4x STS.32.
    // Halo columns cx=0 / cx=33 are reflect copies of px 1 / px 30.
    {
        const int c = l >> 3, pxg = l & 7;
        for (int u = wrp; u < 48; u += 8) {
            int ry = u >> 3, cb = (u & 7) << 3;    // row, channel block
            int py = refl(row0 - 1 + ry);
            const float4* r0p = (const float4*)(A + (size_t)(cb + 2 * c) * 1024
                                                + py * 32) + pxg;
            const float4* r1p = (const float4*)(A + (size_t)(cb + 2 * c + 1) * 1024
                                                + py * 32) + pxg;
            float4 e = *r0p, o = *r1p;
            uint32_t w0, w1, w2, w3;
            CVT_F16X2(w0, e.x, o.x);
            CVT_F16X2(w1, e.y, o.y);
            CVT_F16X2(w2, e.z, o.z);
            CVT_F16X2(w3, e.w, o.w);
            uint32_t base = sb + SM_HI +
                (uint32_t)((ry * 34 + 1 + 4 * pxg) * 144 + ((cb >> 1) + c) * 4);
            STS32(w0, base);
            STS32(w1, base + 144);
            STS32(w2, base + 288);
            STS32(w3, base + 432);
            if (pxg == 0) STS32(w1, base - 144);       // cx=0  <- px 1
            if (pxg == 7) STS32(w2, base + 576);       // cx=33 <- px 30
        }
    }
    __syncthreads();

    // stats from the fp16-rounded plane, then 3x3 box sums
    if (t < 204) {
        const uint4* hip = (const uint4*)(smem + SM_HI + t * 144);
        float s1 = 0.f, s2 = 0.f;
        #pragma unroll
        for (int w = 0; w < 8; ++w) {
            uint4 hv = hip[w];
            const uint32_t* hq = (const uint32_t*)&hv;
            #pragma unroll
            for (int j = 0; j < 4; ++j) {
                __half2 hh = *reinterpret_cast<const __half2*>(&hq[j]);
                float f0 = __low2float(hh), f1 = __high2float(hh);
                s1 += f0 + f1;
                s2 += f0 * f0 + f1 * f1;
            }
        }
        smf[SM_S1 / 4 + t] = s1;
        smf[SM_S2 / 4 + t] = s2;
    }
    __syncthreads();
    if (t < 128) {
        int r = t >> 5, x = t & 31;
        float s1 = 0.f, s2 = 0.f;
        #pragma unroll
        for (int dr = 0; dr < 3; ++dr)
            #pragma unroll
            for (int dc = 0; dc < 3; ++dc) {
                int i = (r + dr) * 34 + x + dc;
                s1 += smf[SM_S1 / 4 + i];
                s2 += smf[SM_S2 / 4 + i];
            }
        float mean = s1 * (1.f / 576.f);
        float var  = (s2 - s1 * s1 * (1.f / 576.f)) * (1.f / 575.f);
        smf[SM_MEAN / 4 + t] = mean;
        smf[SM_RSTD / 4 + t] = rsqrtf(fmaxf(var, 1e-30f));
    }

    // warp tile: image row (wrp>>1), 32 pixels (2 m16 tiles), out half wrp&1
    const int g = l >> 2, tg = l & 3;
    const int row = wrp >> 1, h = wrp & 1;

    // A ldmatrix lane offset (padded 144B rows, proven):
    const uint32_t a_lane =
        (uint32_t)((((l >> 3) & 1) * 8 + (l & 7)) * 144 + ((l >> 4) & 1) * 16);
    // B lane pieces for swizzled 128B rows:
    const uint32_t b_row = (uint32_t)((((l >> 4) & 1) * 8 + (l & 7)) * 128);
    const uint32_t b_sel = (uint32_t)((l >> 3) & 1);
    const uint32_t b_wz  = (uint32_t)(l & 7);

    float acc[2][4][4];
    #pragma unroll
    for (int i = 0; i < 2; ++i)
        #pragma unroll
        for (int j = 0; j < 4; ++j)
            #pragma unroll
            for (int q = 0; q < 4; ++q) acc[i][j][q] = 0.f;

    int buf = 0;
    for (int tap = 0; tap < 9; ++tap) {
        CP_WAIT(0);
        __syncthreads();
        if (tap < 8) {
            const char* src = (const char*)g_wtp + (size_t)(tap + 1) * B_BYTES;
            uint32_t dst = sb + SM_B0 + (buf ^ 1) * B_BYTES;
            for (int i = t; i < B_BYTES / 16; i += 256)
                CP_ASYNC16(dst + i * 16, __cvta_generic_to_global(src + i * 16));
            CP_COMMIT();
        }

        const int dy = tap / 3, dx = tap - dy * 3;
        const uint32_t pixbase = (uint32_t)((row + dy) * 34 + dx) * 144u;
        const uint32_t A0 = sb + SM_HI + pixbase + a_lane;        // tile0
        const uint32_t A1 = A0 + 16 * 144;                        // tile1
        const uint32_t Bh = sb + SM_B0 + buf * B_BYTES + h * 4096 + b_row;

        #pragma unroll
        for (int kc = 0; kc < 4; ++kc) {
            const uint32_t ka = (uint32_t)kc * 32u;
            const uint32_t bcol = ((((uint32_t)kc * 2u + b_sel) ^ b_wz) << 4);
            uint32_t ah00, ah01, ah02, ah03, ah10, ah11, ah12, ah13;
            LDSM_X4(ah00, ah01, ah02, ah03, A0 + ka);
            LDSM_X4(ah10, ah11, ah12, ah13, A1 + ka);

            #pragma unroll
            for (int j = 0; j < 2; ++j) {
                uint32_t bh0, bh1, bh2, bh3;
                LDSM_X4(bh0, bh1, bh2, bh3, Bh + (uint32_t)(j * 2048) + bcol);
                MMA16816(acc[0][2 * j],     ah00, ah01, ah02, ah03, bh0, bh1);
                MMA16816(acc[1][2 * j],     ah10, ah11, ah12, ah13, bh0, bh1);
                MMA16816(acc[0][2 * j + 1], ah00, ah01, ah02, ah03, bh2, bh3);
                MMA16816(acc[1][2 * j + 1], ah10, ah11, ah12, ah13, bh2, bh3);
            }
        }
        buf ^= 1;
    }

    // epilogue: (acc - mean*wsum) * rstd
    float* ob = out + (size_t)b * 65536 + (size_t)(row0 + row) * 32;
    #pragma unroll
    for (int t2 = 0; t2 < 2; ++t2) {
        const int x0 = t2 * 16 + g;
        const int pp = row * 32 + x0;
        const float mean0 = smf[SM_MEAN / 4 + pp],     rstd0 = smf[SM_RSTD / 4 + pp];
        const float mean1 = smf[SM_MEAN / 4 + pp + 8], rstd1 = smf[SM_RSTD / 4 + pp + 8];
        #pragma unroll
        for (int nc = 0; nc < 4; ++nc) {
            const int o0 = h * 32 + nc * 8 + tg * 2;
            const float ws0 = smf[SM_WSUM / 4 + o0];
            const float ws1 = smf[SM_WSUM / 4 + o0 + 1];
            ob[(size_t)o0 * 1024 + x0]           = (acc[t2][nc][0] - mean0 * ws0) * rstd0;
            ob[(size_t)(o0 + 1) * 1024 + x0]     = (acc[t2][nc][1] - mean0 * ws1) * rstd0;
            ob[(size_t)o0 * 1024 + x0 + 8]       = (acc[t2][nc][2] - mean1 * ws0) * rstd1;
            ob[(size_t)(o0 + 1) * 1024 + x0 + 8] = (acc[t2][nc][3] - mean1 * ws1) * rstd1;
        }
    }
}

extern "C" void kernel_launch(void* const* d_in, const int* in_sizes, int n_in,
                              void* d_out, int out_size) {
    const float* a = (const float*)d_in[0];   // [256,64,32,32]
    const float* w = (const float*)d_in[1];   // [576,64]
    float* out = (float*)d_out;

    cudaFuncSetAttribute(conv_mma_kernel,
                         cudaFuncAttributeMaxDynamicSharedMemorySize, SMEM_TOTAL);

    prep_kernel<<<145, 256>>>(w);
    conv_mma_kernel<<<2048, 256, SMEM_TOTAL>>>(a, out);
}